// round 15
// baseline (speedup 1.0000x reference)
#include <cuda_runtime.h>
#include <cuda_fp16.h>
#include <mma.h>
#include <math.h>
#include <stdint.h>

using namespace nvcuda;

#define Bdim 4
#define Cdim 64
#define Hdim 128
#define Wdim 128
#define HW (Hdim*Wdim)

#define PADH 72            // halfs per smem row for B tiles (144 B)

// ---------------------------------------------------------------------------
// Device scratch
// ---------------------------------------------------------------------------
__device__ uint4 t1Th[Bdim*HW*8];       // half [pix][64ch] (offset path)
__device__ uint4 t2Th[Bdim*HW*8];       // half [pix][64ch] (mask path)
__device__ uint4 g_x8[Bdim*8*HW];       // half x, channel-oct packed: [b][c8][pix]
__device__ uint4 wB2o[2304];            // half [9 tap][32 cout][64 cin] (w_off2, rows 18-31 zero)
__device__ uint4 wB2m[2304];            // half [9 tap][32 cout][64 cin] (w_mask2, rows 9-31 zero)
__device__ float g_off [Bdim*18*HW];
__device__ float g_mask[Bdim*9*HW];
__device__ float g_pre [Bdim*Cdim*HW];
__device__ float2 g_part[2048*32];      // per-warp-slot per-group partial (sum, sumsq)

// ---------------------------------------------------------------------------
// Kernel 1: both 1x1 convs as one wmma GEMM; emits g_x8 (oct-packed x).
// Also performs (distributed) wB2o/wB2m prep and inline w1 conversion,
// replacing the old k0_prep kernel.
// ---------------------------------------------------------------------------
#define K1_A    0
#define K1_B    18432                  // 128*144
#define K1_STG  36864
#define K1_SMEM (36864 + 34816)        // 71680 B

__global__ __launch_bounds__(256, 3) void k1_wmma(
    const float* __restrict__ x,
    const float* __restrict__ w_off1, const float* __restrict__ w_mask1,
    const float* __restrict__ w_off2, const float* __restrict__ w_mask2)
{
    extern __shared__ char sm[];
    __half* Ah = (__half*)(sm + K1_A);
    __half* Bh = (__half*)(sm + K1_B);
    float*  Sg = (float*) (sm + K1_STG);
    const int tid = threadIdx.x;
    const int wid = tid >> 5, lid = tid & 31;
    const int p0  = blockIdx.x * 128;
    const int b   = p0 >> 14;
    const int pi  = p0 & 16383;

    // distributed wB2 prep (blocks 0..143 convert one half each/thread)
    {
        int j = blockIdx.x * 256 + tid;
        if (j < 18432) {
            int t = j >> 11, o = (j >> 6) & 31, c = j & 63;
            ((__half*)wB2o)[j] = __float2half_rn((o < 18) ? w_off2[o*576 + c*9 + t] : 0.f);
        } else if (j < 36864) {
            int j2 = j - 18432;
            int t = j2 >> 11, o = (j2 >> 6) & 31, c = j2 & 63;
            ((__half*)wB2m)[j2] = __float2half_rn((o < 9) ? w_mask2[o*576 + c*9 + t] : 0.f);
        }
    }

    // B tile: inline convert w_off1 (couts 0-63) | w_mask1 (couts 64-127)
    for (int j = tid; j < 8192; j += 256) {
        int o = j >> 6, c = j & 63;
        float v = (o < 64) ? w_off1[o*64 + c] : w_mask1[(o-64)*64 + c];
        *(__half*)((char*)Bh + o*144 + c*2) = __float2half_rn(v);
    }
    const float* xb = x + (size_t)b * 64 * HW + pi;
    for (int j = tid; j < 4096; j += 256) {
        int cp = j >> 7, p = j & 127;
        float va = xb[(2*cp  )*HW + p];
        float vb = xb[(2*cp+1)*HW + p];
        __half2 h = __floats2half2_rn(va, vb);
        *(uint32_t*)((char*)Ah + p*144 + cp*4) = *(uint32_t*)&h;
    }
    __syncthreads();

    // emit oct-packed x gather table
    for (int j = tid; j < 1024; j += 256) {
        int c8 = j >> 7, p = j & 127;
        uint4 v = *(uint4*)((char*)Ah + p*144 + c8*16);
        g_x8[(size_t)((b*8 + c8) << 14) + pi + p] = v;
    }

    float* st = Sg + wid*16*68;
    for (int half = 0; half < 2; half++) {
        wmma::fragment<wmma::accumulator, 16, 16, 16, float> acc[4];
#pragma unroll
        for (int n = 0; n < 4; n++) wmma::fill_fragment(acc[n], 0.f);
#pragma unroll
        for (int k = 0; k < 4; k++) {
            wmma::fragment<wmma::matrix_a, 16, 16, 16, __half, wmma::row_major> fa;
            wmma::load_matrix_sync(fa, Ah + wid*16*PADH + k*16, PADH);
#pragma unroll
            for (int n = 0; n < 4; n++) {
                wmma::fragment<wmma::matrix_b, 16, 16, 16, __half, wmma::col_major> fb;
                wmma::load_matrix_sync(fb, Bh + (half*4 + n)*16*PADH + k*16, PADH);
                wmma::mma_sync(acc[n], fa, fb, acc[n]);
            }
        }
#pragma unroll
        for (int n = 0; n < 4; n++)
            wmma::store_matrix_sync(st + n*16, acc[n], 68, wmma::mem_row_major);
        __syncwarp();
#pragma unroll
        for (int i = 0; i < 4; i++) {
            int item  = i*32 + lid;
            int row   = item >> 3;
            int chunk = item & 7;
            const float* s = st + row*68 + chunk*8;
            uint4 o4;
            __half2 h;
            h = __floats2half2_rn(s[0], s[1]); o4.x = *(uint32_t*)&h;
            h = __floats2half2_rn(s[2], s[3]); o4.y = *(uint32_t*)&h;
            h = __floats2half2_rn(s[4], s[5]); o4.z = *(uint32_t*)&h;
            h = __floats2half2_rn(s[6], s[7]); o4.w = *(uint32_t*)&h;
            int gp = p0 + wid*16 + row;
            if (half == 0) t1Th[(size_t)gp*8 + chunk] = o4;
            else           t2Th[(size_t)gp*8 + chunk] = o4;
        }
        __syncwarp();
    }
}

// ---------------------------------------------------------------------------
// Kernel 2: 3x3 convs, 2 output rows/block, 8 warps of 32px x 32couts.
// A: 4 dy-row sections, 130 px, 160B pixel stride (32B-aligned dx shifts).
// B path0: tap-packed 18-row sections (2592B/tap).
// ---------------------------------------------------------------------------
#define K2_ASEC  20800                 // 130*160 bytes per dy section
#define K2_B     83200                 // 4*20800
#define K2_SMEM  (83200 + 25344)       // 108544 B -> 2 CTAs/SM

__global__ __launch_bounds__(256) void k2_wmma()
{
    extern __shared__ char sm[];
    __half* Ah = (__half*)sm;
    __half* Bh = (__half*)(sm + K2_B);
    float*  Sg = (float*)sm;             // overlay on A after MMA phase
    const int tid = threadIdx.x;
    const int wid = tid >> 5, lid = tid & 31;
    const int b  = blockIdx.x >> 6;
    const int y0 = (blockIdx.x & 63) * 2;
    const int path = blockIdx.y;

    if (path == 0) {
        for (int j = tid; j < 1296; j += 256) {
            int t = j / 144, r = j - t*144;
            int o = r >> 3, seg = r & 7;
            *(uint4*)((char*)Bh + t*2592 + o*144 + seg*16) = wB2o[t*256 + o*8 + seg];
        }
    } else {
        for (int j = tid; j < 1152; j += 256) {
            int t = j >> 7, r = j & 127;
            int o = r >> 3, seg = r & 7;
            *(uint4*)((char*)Bh + t*2304 + o*144 + seg*16) = wB2m[t*256 + o*8 + seg];
        }
    }
    const uint4* src = path ? t2Th : t1Th;
    const uint4 z4 = make_uint4(0u,0u,0u,0u);
    for (int j = tid; j < 4160; j += 256) {      // 4 rows * 130 px * 8 segs
        int d = j / 1040, r = j - d*1040;
        int p = r >> 3, seg = r & 7;
        int yy = y0 + d - 1;
        int px = p - 1;
        uint4 v = z4;
        if ((unsigned)yy < 128u && (unsigned)px < 128u)
            v = src[(size_t)((b << 14) + (yy << 7) + px) * 8 + seg];
        *(uint4*)((char*)Ah + d*K2_ASEC + p*160 + seg*16) = v;
    }
    __syncthreads();

    const int rl  = wid >> 2;
    const int px0 = (wid & 3) * 32;

    if (path == 0) {
        wmma::fragment<wmma::accumulator, 16, 16, 16, float> acc[2][2];
        wmma::fill_fragment(acc[0][0], 0.f);
        wmma::fill_fragment(acc[0][1], 0.f);
        wmma::fill_fragment(acc[1][0], 0.f);
        wmma::fill_fragment(acc[1][1], 0.f);
        for (int dy = 0; dy < 3; dy++) {
#pragma unroll
            for (int dx = 0; dx < 3; dx++) {
                const __half* Ad = Ah + (rl + dy)*(K2_ASEC/2) + (px0 + dx)*80;
                const __half* Bt = Bh + (dy*3 + dx)*1296;
#pragma unroll
                for (int k = 0; k < 4; k++) {
                    wmma::fragment<wmma::matrix_a, 16, 16, 16, __half, wmma::row_major> fa0, fa1;
                    wmma::load_matrix_sync(fa0, Ad + k*16, 80);
                    wmma::load_matrix_sync(fa1, Ad + 16*80 + k*16, 80);
                    wmma::fragment<wmma::matrix_b, 16, 16, 16, __half, wmma::col_major> fb0, fb1;
                    wmma::load_matrix_sync(fb0, Bt + k*16, PADH);
                    wmma::load_matrix_sync(fb1, Bt + 16*PADH + k*16, PADH);
                    wmma::mma_sync(acc[0][0], fa0, fb0, acc[0][0]);
                    wmma::mma_sync(acc[0][1], fa0, fb1, acc[0][1]);
                    wmma::mma_sync(acc[1][0], fa1, fb0, acc[1][0]);
                    wmma::mma_sync(acc[1][1], fa1, fb1, acc[1][1]);
                }
            }
        }
        __syncthreads();
        float* st = Sg + (rl*128 + px0)*36;
        wmma::store_matrix_sync(st,            acc[0][0], 36, wmma::mem_row_major);
        wmma::store_matrix_sync(st + 16,       acc[0][1], 36, wmma::mem_row_major);
        wmma::store_matrix_sync(st + 16*36,    acc[1][0], 36, wmma::mem_row_major);
        wmma::store_matrix_sync(st + 16*36+16, acc[1][1], 36, wmma::mem_row_major);
        __syncwarp();
        const int p_ = lid & 15;
        const int oh = lid >> 4;
#pragma unroll
        for (int pa = 0; pa < 2; pa++) {
            const float* s = st + (pa*16 + p_)*36;
            int pix = (y0 + rl)*Wdim + px0 + pa*16 + p_;
#pragma unroll
            for (int j = 0; j < 9; j++) {
                int o = oh*9 + j;
                g_off[((size_t)b*18 + o)*HW + pix] = s[o];
            }
        }
    } else {
        wmma::fragment<wmma::accumulator, 16, 16, 16, float> acc[2];
        wmma::fill_fragment(acc[0], 0.f);
        wmma::fill_fragment(acc[1], 0.f);
        for (int dy = 0; dy < 3; dy++) {
#pragma unroll
            for (int dx = 0; dx < 3; dx++) {
                const __half* Ad = Ah + (rl + dy)*(K2_ASEC/2) + (px0 + dx)*80;
                const __half* Bt = Bh + (dy*3 + dx)*1152;
#pragma unroll
                for (int k = 0; k < 4; k++) {
                    wmma::fragment<wmma::matrix_a, 16, 16, 16, __half, wmma::row_major> fa0, fa1;
                    wmma::load_matrix_sync(fa0, Ad + k*16, 80);
                    wmma::load_matrix_sync(fa1, Ad + 16*80 + k*16, 80);
                    wmma::fragment<wmma::matrix_b, 16, 16, 16, __half, wmma::col_major> fb;
                    wmma::load_matrix_sync(fb, Bt + k*16, PADH);
                    wmma::mma_sync(acc[0], fa0, fb, acc[0]);
                    wmma::mma_sync(acc[1], fa1, fb, acc[1]);
                }
            }
        }
        __syncthreads();
        float* st = Sg + (rl*128 + px0)*36;
        wmma::store_matrix_sync(st,         acc[0], 36, wmma::mem_row_major);
        wmma::store_matrix_sync(st + 16*36, acc[1], 36, wmma::mem_row_major);
        __syncwarp();
        const int p_ = lid & 15;
        const int oh = lid >> 4;
        if (oh == 0) {
#pragma unroll
            for (int pa = 0; pa < 2; pa++) {
                const float* s = st + (pa*16 + p_)*36;
                int pix = (y0 + rl)*Wdim + px0 + pa*16 + p_;
#pragma unroll
                for (int j = 0; j < 9; j++) {
                    float v = s[j];
                    g_mask[((size_t)b*9 + j)*HW + pix] = 1.f / (1.f + expf(-v));
                }
            }
        }
    }
}

// ---------------------------------------------------------------------------
// Kernel 3: deformable gather (8-channel LDG.128) + einsum + bias,
// fused groupnorm partials. (52 regs, 2 CTAs/SM.)
// ---------------------------------------------------------------------------
__global__ __launch_bounds__(512) void k3_sample(
    const float* __restrict__ wgt,
    const float* __restrict__ bias)
{
    __shared__ float4 sw8[9*8*2];       // [k][cg] weight oct (2x float4)
    __shared__ float  sb[64];
    __shared__ int4   sI[9*64];
    __shared__ float4 sC[9*64];

    const int tid = threadIdx.x;
    if (tid < 144) {
        int k = tid / 16, idx = tid & 15;
        int cg = idx >> 1, h = idx & 1;
        int c0 = cg*8 + h*4;
        sw8[(k*8 + cg)*2 + h] = make_float4(wgt[(c0  )*9 + k], wgt[(c0+1)*9 + k],
                                            wgt[(c0+2)*9 + k], wgt[(c0+3)*9 + k]);
    }
    if (tid >= 448) sb[tid - 448] = bias[tid - 448];

    const int blk = blockIdx.x;             // 1024
    const int b   = blk >> 8;
    const int p0  = (blk & 255) * 64;

    for (int e = tid; e < 576; e += 512) {
        const int k = e >> 6;
        const int p = e & 63;
        const int pix = p0 + p;
        const int gy = pix >> 7, gx = pix & 127;
        const float* offb = g_off  + (size_t)b * 18 * HW;
        const float* mkb  = g_mask + (size_t)b * 9  * HW;
        float oy = offb[(2*k  )*HW + pix];
        float ox = offb[(2*k+1)*HW + pix];
        float mk = mkb [ k     *HW + pix];
        float py  = oy + (float)gy + (float)(k/3 - 1);
        float pxx = ox + (float)gx + (float)(k%3 - 1);
        float y0f = floorf(py),  x0f = floorf(pxx);
        float wy1 = py - y0f,    wx1 = pxx - x0f;
        int   y0  = (int)y0f,    xx0 = (int)x0f;
        int cy0 = min(max(y0,   0), Hdim-1), cy1 = min(max(y0+1, 0), Hdim-1);
        int cx0 = min(max(xx0,  0), Wdim-1), cx1 = min(max(xx0+1,0), Wdim-1);
        float vy0 = (y0   >= 0 && y0   < Hdim) ? 1.f : 0.f;
        float vy1 = (y0+1 >= 0 && y0+1 < Hdim) ? 1.f : 0.f;
        float vx0 = (xx0  >= 0 && xx0  < Wdim) ? 1.f : 0.f;
        float vx1 = (xx0+1>= 0 && xx0+1< Wdim) ? 1.f : 0.f;
        float ay0 = (1.f - wy1) * vy0 * mk;
        float ay1 = wy1 * vy1 * mk;
        float ax0 = (1.f - wx1) * vx0;
        float ax1 = wx1 * vx1;
        sI[k*64 + p] = make_int4(cy0*Wdim + cx0, cx1 - cx0, (cy1 - cy0)*Wdim, 0);
        sC[k*64 + p] = make_float4(ay0*ax0, ay0*ax1, ay1*ax0, ay1*ax1);
    }
    __syncthreads();

    const int p   = tid & 63;
    const int cg  = tid >> 6;
    const int pix = p0 + p;
    const uint4* x8 = g_x8 + (size_t)((b*8 + cg) << 14);

    float a0=0.f,a1=0.f,a2=0.f,a3=0.f,a4=0.f,a5=0.f,a6=0.f,a7=0.f;
    for (int k = 0; k < 9; k++) {
        int4   I  = sI[k*64 + p];
        float4 C  = sC[k*64 + p];
        float4 Wa = sw8[(k*8 + cg)*2];
        float4 Wb = sw8[(k*8 + cg)*2 + 1];
        uint4 u00 = __ldg(x8 + I.x);
        uint4 u01 = __ldg(x8 + I.x + I.y);
        uint4 u10 = __ldg(x8 + I.x + I.z);
        uint4 u11 = __ldg(x8 + I.x + I.z + I.y);
        float2 f00, f01, f10, f11;
        float s;
        f00 = __half22float2(*(__half2*)&u00.x); f01 = __half22float2(*(__half2*)&u01.x);
        f10 = __half22float2(*(__half2*)&u10.x); f11 = __half22float2(*(__half2*)&u11.x);
        s = C.x*f00.x; s = fmaf(C.y,f01.x,s); s = fmaf(C.z,f10.x,s); s = fmaf(C.w,f11.x,s); a0 = fmaf(Wa.x, s, a0);
        s = C.x*f00.y; s = fmaf(C.y,f01.y,s); s = fmaf(C.z,f10.y,s); s = fmaf(C.w,f11.y,s); a1 = fmaf(Wa.y, s, a1);
        f00 = __half22float2(*(__half2*)&u00.y); f01 = __half22float2(*(__half2*)&u01.y);
        f10 = __half22float2(*(__half2*)&u10.y); f11 = __half22float2(*(__half2*)&u11.y);
        s = C.x*f00.x; s = fmaf(C.y,f01.x,s); s = fmaf(C.z,f10.x,s); s = fmaf(C.w,f11.x,s); a2 = fmaf(Wa.z, s, a2);
        s = C.x*f00.y; s = fmaf(C.y,f01.y,s); s = fmaf(C.z,f10.y,s); s = fmaf(C.w,f11.y,s); a3 = fmaf(Wa.w, s, a3);
        f00 = __half22float2(*(__half2*)&u00.z); f01 = __half22float2(*(__half2*)&u01.z);
        f10 = __half22float2(*(__half2*)&u10.z); f11 = __half22float2(*(__half2*)&u11.z);
        s = C.x*f00.x; s = fmaf(C.y,f01.x,s); s = fmaf(C.z,f10.x,s); s = fmaf(C.w,f11.x,s); a4 = fmaf(Wb.x, s, a4);
        s = C.x*f00.y; s = fmaf(C.y,f01.y,s); s = fmaf(C.z,f10.y,s); s = fmaf(C.w,f11.y,s); a5 = fmaf(Wb.y, s, a5);
        f00 = __half22float2(*(__half2*)&u00.w); f01 = __half22float2(*(__half2*)&u01.w);
        f10 = __half22float2(*(__half2*)&u10.w); f11 = __half22float2(*(__half2*)&u11.w);
        s = C.x*f00.x; s = fmaf(C.y,f01.x,s); s = fmaf(C.z,f10.x,s); s = fmaf(C.w,f11.x,s); a6 = fmaf(Wb.z, s, a6);
        s = C.x*f00.y; s = fmaf(C.y,f01.y,s); s = fmaf(C.z,f10.y,s); s = fmaf(C.w,f11.y,s); a7 = fmaf(Wb.w, s, a7);
    }

    const int c0 = cg*8;
    float v0 = a0 + sb[c0  ], v1 = a1 + sb[c0+1];
    float v2 = a2 + sb[c0+2], v3 = a3 + sb[c0+3];
    float v4 = a4 + sb[c0+4], v5 = a5 + sb[c0+5];
    float v6 = a6 + sb[c0+6], v7 = a7 + sb[c0+7];
    g_pre[((size_t)b*64 + c0    )*HW + pix] = v0;
    g_pre[((size_t)b*64 + c0 + 1)*HW + pix] = v1;
    g_pre[((size_t)b*64 + c0 + 2)*HW + pix] = v2;
    g_pre[((size_t)b*64 + c0 + 3)*HW + pix] = v3;
    g_pre[((size_t)b*64 + c0 + 4)*HW + pix] = v4;
    g_pre[((size_t)b*64 + c0 + 5)*HW + pix] = v5;
    g_pre[((size_t)b*64 + c0 + 6)*HW + pix] = v6;
    g_pre[((size_t)b*64 + c0 + 7)*HW + pix] = v7;
    float s0 = v0+v1, q0 = fmaf(v0,v0, v1*v1);
    float s1 = v2+v3, q1 = fmaf(v2,v2, v3*v3);
    float s2 = v4+v5, q2 = fmaf(v4,v4, v5*v5);
    float s3 = v6+v7, q3 = fmaf(v6,v6, v7*v7);
#pragma unroll
    for (int o = 16; o > 0; o >>= 1) {
        s0 += __shfl_xor_sync(0xFFFFFFFF, s0, o);
        q0 += __shfl_xor_sync(0xFFFFFFFF, q0, o);
        s1 += __shfl_xor_sync(0xFFFFFFFF, s1, o);
        q1 += __shfl_xor_sync(0xFFFFFFFF, q1, o);
        s2 += __shfl_xor_sync(0xFFFFFFFF, s2, o);
        q2 += __shfl_xor_sync(0xFFFFFFFF, q2, o);
        s3 += __shfl_xor_sync(0xFFFFFFFF, s3, o);
        q3 += __shfl_xor_sync(0xFFFFFFFF, q3, o);
    }
    if ((tid & 31) == 0) {
        int wslot = (tid >> 5) & 1;
        float2* dst = &g_part[((size_t)blk*2 + wslot)*32 + 4*cg];
        dst[0] = make_float2(s0, q0);
        dst[1] = make_float2(s1, q1);
        dst[2] = make_float2(s2, q2);
        dst[3] = make_float2(s3, q3);
    }
}

// ---------------------------------------------------------------------------
// Kernel 4: per-block stats reduce (same summation order as old k4a) +
// normalize + affine + exact GELU (float4). One kernel, no k4a.
// Each block spans 1024 consecutive floats -> single (b, c) -> single group.
// ---------------------------------------------------------------------------
__global__ __launch_bounds__(256) void k4_norm(
    const float* __restrict__ gamma,
    const float* __restrict__ beta,
    float* __restrict__ out)
{
    __shared__ float2 sp[256];
    __shared__ float s_mean, s_rstd;
    const int tid = threadIdx.x;
    const int blk = blockIdx.x;
    const int i0  = blk << 10;              // first float index of this block
    const int c   = (i0 >> 14) & 63;
    const int b   = i0 >> 20;
    const int g   = c >> 1;

    // reduce 512 partial slots for (b,g) -- identical order to old k4a
    float s = 0.f, q = 0.f;
    for (int j = tid; j < 512; j += 256) {
        float2 v = g_part[(size_t)(b*512 + j)*32 + g];
        s += v.x; q += v.y;
    }
    sp[tid] = make_float2(s, q);
    __syncthreads();
    for (int st = 128; st > 0; st >>= 1) {
        if (tid < st) {
            sp[tid].x += sp[tid + st].x;
            sp[tid].y += sp[tid + st].y;
        }
        __syncthreads();
    }
    if (tid == 0) {
        float mean = sp[0].x * (1.f/32768.f);
        float var  = sp[0].y * (1.f/32768.f) - mean*mean;
        s_mean = mean;
        s_rstd = rsqrtf(var + 1e-5f);
    }
    __syncthreads();

    const float mean = s_mean;
    const float rstd = s_rstd;
    const float ga = __ldg(gamma + c), be = __ldg(beta + c);
    const int i4 = blk * 256 + tid;
    float4 v = ((const float4*)g_pre)[i4];
    float4 r;
    float yv;
    yv = (v.x - mean) * rstd * ga + be;
    r.x = 0.5f * yv * (1.f + erff(yv * 0.70710678118654752f));
    yv = (v.y - mean) * rstd * ga + be;
    r.y = 0.5f * yv * (1.f + erff(yv * 0.70710678118654752f));
    yv = (v.z - mean) * rstd * ga + be;
    r.z = 0.5f * yv * (1.f + erff(yv * 0.70710678118654752f));
    yv = (v.w - mean) * rstd * ga + be;
    r.w = 0.5f * yv * (1.f + erff(yv * 0.70710678118654752f));
    ((float4*)out)[i4] = r;
}

// ---------------------------------------------------------------------------
extern "C" void kernel_launch(void* const* d_in, const int* in_sizes, int n_in,
                              void* d_out, int out_size)
{
    const float* x       = (const float*)d_in[0];
    const float* w_off1  = (const float*)d_in[1];
    const float* w_off2  = (const float*)d_in[2];
    const float* w_mask1 = (const float*)d_in[3];
    const float* w_mask2 = (const float*)d_in[4];
    const float* weight  = (const float*)d_in[5];
    const float* bias    = (const float*)d_in[6];
    const float* gamma   = (const float*)d_in[7];
    const float* beta    = (const float*)d_in[8];
    float* out = (float*)d_out;

    cudaFuncSetAttribute(k1_wmma, cudaFuncAttributeMaxDynamicSharedMemorySize, K1_SMEM);
    cudaFuncSetAttribute(k2_wmma, cudaFuncAttributeMaxDynamicSharedMemorySize, K2_SMEM);

    k1_wmma <<<512, 256, K1_SMEM>>>(x, w_off1, w_mask1, w_off2, w_mask2);
    k2_wmma <<<dim3(256, 2), 256, K2_SMEM>>>();
    k3_sample<<<1024, 512>>>(weight, bias);
    k4_norm <<<4096, 256>>>(gamma, beta, out);
}